// round 6
// baseline (speedup 1.0000x reference)
#include <cuda_runtime.h>
#include <cuda_bf16.h>
#include <cuda_fp16.h>
#include <cstdint>

// Problem dims
#define MDIM 8192
#define KDIM 4096
#define NDIM 11008

// Tiling: CTA 256x128x64, 8 warps as 4(M) x 2(N), warp tile 64x64
#define BM 256
#define BN 128
#define BK 64
#define KT 64                  // k-tiles per output tile (KDIM/BK)
#define NTM (MDIM / BM)        // 32
#define NTN (NDIM / BN)        // 86
#define NTILES (NTM * NTN)     // 2752
#define NCTA 148
#define STAGES 4

// Padded smem: rows of 64 fp16 padded to 72 (144B) for conflict-free ldmatrix
#define PITCH_B 144
#define A_TILE_B (BM * PITCH_B)          // 36864
#define W_TILE_B (BN * PITCH_B)          // 18432
#define STAGE_B  (A_TILE_B + W_TILE_B)   // 55296
#define SMEM_TOTAL (STAGES * STAGE_B)    // 221184

// ---------------------------------------------------------------------------
// Static scratch (no allocs allowed)
// ---------------------------------------------------------------------------
__device__ __half g_X[(size_t)MDIM * KDIM];
__device__ __half g_W[(size_t)NDIM * KDIM];

__device__ __forceinline__ uint32_t smem_u32(const void* p) {
    uint32_t a;
    asm("{ .reg .u64 t; cvta.to.shared.u64 t, %1; cvt.u32.u64 %0, t; }" : "=r"(a) : "l"(p));
    return a;
}

__device__ __forceinline__ void cp16(uint32_t s, const void* g) {
    asm volatile("cp.async.cg.shared.global [%0], [%1], 16;" :: "r"(s), "l"(g));
}

__device__ __forceinline__ void ldsm4(uint32_t* r, uint32_t a) {
    asm volatile("ldmatrix.sync.aligned.m8n8.x4.shared.b16 {%0,%1,%2,%3}, [%4];"
                 : "=r"(r[0]), "=r"(r[1]), "=r"(r[2]), "=r"(r[3]) : "r"(a));
}

__device__ __forceinline__ void mma16816(float* d, const uint32_t* a, uint32_t b0, uint32_t b1) {
    asm volatile(
        "mma.sync.aligned.m16n8k16.row.col.f32.f16.f16.f32 "
        "{%0,%1,%2,%3}, {%4,%5,%6,%7}, {%8,%9}, {%0,%1,%2,%3};"
        : "+f"(d[0]), "+f"(d[1]), "+f"(d[2]), "+f"(d[3])
        : "r"(a[0]), "r"(a[1]), "r"(a[2]), "r"(a[3]), "r"(b0), "r"(b1));
}

// ---------------------------------------------------------------------------
// Pre-pass converts
// ---------------------------------------------------------------------------
__global__ void __launch_bounds__(256) convert_x_kernel(const float4* __restrict__ x) {
    int i = blockIdx.x * blockDim.x + threadIdx.x;
    if (i >= (MDIM * KDIM / 4)) return;
    float4 v = x[i];
    __half2* xp = reinterpret_cast<__half2*>(g_X);
    __half2 a, b;
    a.x = __float2half_rn(v.x); a.y = __float2half_rn(v.y);
    b.x = __float2half_rn(v.z); b.y = __float2half_rn(v.w);
    xp[2*i] = a; xp[2*i+1] = b;
}

__global__ void __launch_bounds__(256) convert_w_kernel(const int4* __restrict__ w) {
    int i = blockIdx.x * blockDim.x + threadIdx.x;
    if (i >= (NDIM * KDIM / 4)) return;
    int4 v = w[i];
    __half2 a, b;
    a.x = __float2half_rn((float)v.x);   // int8 range: exact in fp16
    a.y = __float2half_rn((float)v.y);
    b.x = __float2half_rn((float)v.z);
    b.y = __float2half_rn((float)v.w);
    __half2* wp = reinterpret_cast<__half2*>(g_W);
    wp[2*i] = a; wp[2*i+1] = b;
}

// ---------------------------------------------------------------------------
// Persistent GEMM: 148 CTAs, continuous cp.async stream across tiles
// ---------------------------------------------------------------------------
__global__ void __launch_bounds__(256, 1)
qlinear_gemm(const float* __restrict__ wscale,
             const float* __restrict__ wbias,
             float* __restrict__ out)
{
    extern __shared__ char smem[];
    const uint32_t sb = smem_u32(smem);
    const int tid = threadIdx.x;
    const int wid = tid >> 5;
    const int lane = tid & 31;
    const int wm = wid >> 1;   // 0..3 -> 64 rows
    const int wn = wid & 1;    // 0..1 -> 64 cols
    const int cta = blockIdx.x;

    // my tile count (static schedule: gid = cta + NCTA*i)
    int my_ntiles = 0;
    for (int g = cta; g < NTILES; g += NCTA) my_ntiles++;
    const int my_iters = my_ntiles * KT;

    // per-thread load coords
    const int lrow0 = tid >> 3;       // 0..31
    const int lcol  = tid & 7;        // 16B chunk within 128B row

    // issue loads for flat iteration j (stage j&3)
    auto load_stage = [&](int j) {
        const int tl  = j >> 6;               // local tile index (KT=64)
        const int kt  = j & 63;
        const int gid = cta + NCTA * tl;
        const int m0  = (gid / NTN) * BM;
        const int n0  = (gid % NTN) * BN;
        const __half* gX = g_X + (size_t)m0 * KDIM + kt * BK;
        const __half* gW = g_W + (size_t)n0 * KDIM + kt * BK;
        const uint32_t base = sb + (j & 3) * STAGE_B;
        #pragma unroll
        for (int i = 0; i < 8; i++) {
            const int r = lrow0 + i * 32;
            cp16(base + r * PITCH_B + lcol * 16, gX + (size_t)r * KDIM + lcol * 8);
        }
        #pragma unroll
        for (int i = 0; i < 4; i++) {
            const int r = lrow0 + i * 32;
            cp16(base + A_TILE_B + r * PITCH_B + lcol * 16, gW + (size_t)r * KDIM + lcol * 8);
        }
    };

    float acc[4][8][4];
    #pragma unroll
    for (int a = 0; a < 4; a++)
        #pragma unroll
        for (int b = 0; b < 8; b++)
            #pragma unroll
            for (int c = 0; c < 4; c++) acc[a][b][c] = 0.f;

    // Prologue: 3 stages
    load_stage(0);
    asm volatile("cp.async.commit_group;" ::: "memory");
    load_stage(1);
    asm volatile("cp.async.commit_group;" ::: "memory");
    load_stage(2);
    asm volatile("cp.async.commit_group;" ::: "memory");

    const int lr = lane & 15;
    const int lk = (lane >> 4) * 16;

    for (int j = 0; j < my_iters; j++) {
        asm volatile("cp.async.wait_group 2;" ::: "memory");
        __syncthreads();
        if (j + 3 < my_iters) load_stage(j + 3);
        asm volatile("cp.async.commit_group;" ::: "memory");

        // compute stage j&3
        {
            const uint32_t abase = sb + (j & 3) * STAGE_B;
            const uint32_t bbase = abase + A_TILE_B;
            #pragma unroll
            for (int ks = 0; ks < 4; ks++) {
                uint32_t af[4][4], bf[4][4];
                #pragma unroll
                for (int mt = 0; mt < 4; mt++) {
                    uint32_t ro = (uint32_t)(wm * 64 + mt * 16 + lr) * PITCH_B + ks * 32 + lk;
                    ldsm4(af[mt], abase + ro);
                }
                #pragma unroll
                for (int nt = 0; nt < 4; nt++) {
                    uint32_t ro = (uint32_t)(wn * 64 + nt * 16 + lr) * PITCH_B + ks * 32 + lk;
                    ldsm4(bf[nt], bbase + ro);
                }
                #pragma unroll
                for (int mt = 0; mt < 4; mt++) {
                    #pragma unroll
                    for (int nt = 0; nt < 4; nt++) {
                        mma16816(acc[mt][nt*2+0], af[mt], bf[nt][0], bf[nt][2]);
                        mma16816(acc[mt][nt*2+1], af[mt], bf[nt][1], bf[nt][3]);
                    }
                }
            }
        }

        // Tile boundary: epilogue (overlaps already-issued cp.async of next tile)
        if ((j & 63) == 63) {
            const int gid = cta + NCTA * (j >> 6);
            const int m0  = (gid / NTN) * BM;
            const int n0  = (gid % NTN) * BN;
            #pragma unroll
            for (int mt = 0; mt < 4; mt++) {
                const int r0 = m0 + wm * 64 + mt * 16 + (lane >> 2);
                #pragma unroll
                for (int nt = 0; nt < 4; nt++) {
                    #pragma unroll
                    for (int h = 0; h < 2; h++) {
                        const int n = n0 + wn * 64 + nt * 16 + h * 8 + (lane & 3) * 2;
                        float2 sf = *reinterpret_cast<const float2*>(wscale + n);
                        float2 bf2 = *reinterpret_cast<const float2*>(wbias + n);
                        float* d = acc[mt][nt*2+h];
                        float2 v0, v1;
                        v0.x = d[0] * sf.x + bf2.x;
                        v0.y = d[1] * sf.y + bf2.y;
                        v1.x = d[2] * sf.x + bf2.x;
                        v1.y = d[3] * sf.y + bf2.y;
                        *reinterpret_cast<float2*>(out + (size_t)r0 * NDIM + n) = v0;
                        *reinterpret_cast<float2*>(out + (size_t)(r0 + 8) * NDIM + n) = v1;
                        d[0] = 0.f; d[1] = 0.f; d[2] = 0.f; d[3] = 0.f;
                    }
                }
            }
        }
    }
}

// ---------------------------------------------------------------------------
// Host
// ---------------------------------------------------------------------------
extern "C" void kernel_launch(void* const* d_in, const int* in_sizes, int n_in,
                              void* d_out, int out_size) {
    const float* x  = (const float*)d_in[0];
    const int*   wq = (const int*)d_in[1];
    const float* sc = (const float*)d_in[2];
    const float* bi = (const float*)d_in[3];
    float* out = (float*)d_out;

    convert_x_kernel<<<(MDIM * KDIM / 4 + 255) / 256, 256>>>((const float4*)x);
    convert_w_kernel<<<(NDIM * KDIM / 4 + 255) / 256, 256>>>((const int4*)wq);

    cudaFuncSetAttribute(qlinear_gemm, cudaFuncAttributeMaxDynamicSharedMemorySize, SMEM_TOTAL);
    qlinear_gemm<<<NCTA, 256, SMEM_TOTAL>>>(sc, bi, out);
}